// round 1
// baseline (speedup 1.0000x reference)
#include <cuda_runtime.h>
#include <cuda_bf16.h>
#include <math.h>

#define NN 100000
#define DD 128
#define EE 250000
#define TT 3
#define ND (NN*DD)

// -------- scratch (device globals; no runtime allocation) --------
__device__ float g_feat[ND];
__device__ float g_t1[ND];
__device__ float g_t2[ND];
__device__ float g_key[3*ND];
__device__ float g_ska[3*ND];
__device__ float g_v[3*ND];
__device__ int   g_cnt[TT*NN];
__device__ float g_inv[TT*NN];
__device__ float g_gscale[NN];
__device__ float g_colsum[DD];
__device__ float g_colsq[DD];
__device__ float g_wqa[DD*DD];
__device__ float g_wka[DD*DD];

// -------- kernels --------

__global__ void gather_feat_k(const float* __restrict__ n_emb, const int* __restrict__ ind,
                              float* __restrict__ feat) {
    int idx = blockIdx.x * blockDim.x + threadIdx.x;
    if (idx >= ND) return;
    int n = idx >> 7, f = idx & 127;
    feat[idx] = n_emb[(long)ind[n] * DD + f];
}

__global__ void count_k(const int* __restrict__ dst, int* __restrict__ cnt) {
    int e = blockIdx.x * blockDim.x + threadIdx.x;
    if (e >= TT*EE) return;
    int t = e / EE;
    atomicAdd(&cnt[t * NN + dst[e]], 1);
}

__global__ void prep_k(const int* __restrict__ cnt, float* __restrict__ inv,
                       float* __restrict__ gscale) {
    int n = blockIdx.x * blockDim.x + threadIdx.x;
    if (n >= NN) return;
    int c0 = cnt[n], c1 = cnt[NN + n], c2 = cnt[2*NN + n];
    inv[n]        = 1.f / (float)max(c0, 1);
    inv[NN + n]   = 1.f / (float)max(c1, 1);
    inv[2*NN + n] = 1.f / (float)max(c2, 1);
    gscale[n] = (float)((c0 > 0) + (c1 > 0) + (c2 > 0));
}

__global__ void init_acc_k(const float* __restrict__ feat, const float* __restrict__ gscale,
                           float* __restrict__ acc) {
    int idx = blockIdx.x * blockDim.x + threadIdx.x;
    if (idx >= ND) return;
    acc[idx] = feat[idx] * gscale[idx >> 7];
}

__device__ __forceinline__ void red_add_v4(float* p, float4 v) {
    asm volatile("red.global.add.v4.f32 [%0], {%1,%2,%3,%4};"
                 :: "l"(p), "f"(v.x), "f"(v.y), "f"(v.z), "f"(v.w) : "memory");
}

// GCN message pass: acc[dst] += -feat[src]*emb[t] * inv_cnt
__global__ void gcn_edge_k(const float* __restrict__ feat, const float* __restrict__ emb,
                           const int* __restrict__ src, const int* __restrict__ dst,
                           const float* __restrict__ inv, float* __restrict__ acc) {
    int gw = (blockIdx.x * blockDim.x + threadIdx.x) >> 5;
    int lane = threadIdx.x & 31;
    if (gw >= TT*EE) return;
    int t = gw / EE;
    int s = src[gw], d = dst[gw];
    float w = inv[t * NN + d];
    float4 f = reinterpret_cast<const float4*>(feat + (long)s * DD)[lane];
    float4 e = reinterpret_cast<const float4*>(emb + t * DD)[lane];
    float4 v = make_float4(-f.x*e.x*w, -f.y*e.y*w, -f.z*e.z*w, -f.w*e.w*w);
    red_add_v4(acc + (long)d * DD + lane*4, v);
}

// Attention key pass: key[t][dst] += feat[src]*emb[t] * inv_cnt
__global__ void attn_edge_k(const float* __restrict__ feat, const float* __restrict__ emb,
                            const int* __restrict__ src, const int* __restrict__ dst,
                            const float* __restrict__ inv, float* __restrict__ key) {
    int gw = (blockIdx.x * blockDim.x + threadIdx.x) >> 5;
    int lane = threadIdx.x & 31;
    if (gw >= TT*EE) return;
    int t = gw / EE;
    int s = src[gw], d = dst[gw];
    float w = inv[t * NN + d];
    float4 f = reinterpret_cast<const float4*>(feat + (long)s * DD)[lane];
    float4 e = reinterpret_cast<const float4*>(emb + t * DD)[lane];
    float4 v = make_float4(f.x*e.x*w, f.y*e.y*w, f.z*e.z*w, f.w*e.w*w);
    red_add_v4(key + (long)t * ND + (long)d * DD + lane*4, v);
}

// C[M,128] = A[M,128] @ B[128,128]. EPI==1: C[idx] += acc + bias[col]
template<int EPI>
__global__ __launch_bounds__(256) void gemm128(const float* __restrict__ A,
                                               const float* __restrict__ B,
                                               float* __restrict__ C,
                                               const float* __restrict__ bias, int M) {
    __shared__ float As[64][32];
    __shared__ float Bs[32][128];
    int tid = threadIdx.x;
    int ty = tid >> 5, tx = tid & 31;
    int m0 = blockIdx.x * 64;
    float acc[8][4];
    #pragma unroll
    for (int i = 0; i < 8; i++)
        #pragma unroll
        for (int j = 0; j < 4; j++) acc[i][j] = 0.f;

    for (int k0 = 0; k0 < 128; k0 += 32) {
        #pragma unroll
        for (int i = 0; i < 8; i++) {
            int idx = tid + 256 * i;            // 2048 elems
            int r = idx >> 5, kk = idx & 31;
            int row = m0 + r;
            As[r][kk] = (row < M) ? A[(long)row * 128 + k0 + kk] : 0.f;
        }
        #pragma unroll
        for (int i = 0; i < 16; i++) {
            int idx = tid + 256 * i;            // 4096 elems
            int r = idx >> 7, c = idx & 127;
            Bs[r][c] = B[(k0 + r) * 128 + c];
        }
        __syncthreads();
        #pragma unroll
        for (int kk = 0; kk < 32; kk++) {
            float a[8];
            #pragma unroll
            for (int i = 0; i < 8; i++) a[i] = As[ty*8 + i][kk];
            float4 b4 = *reinterpret_cast<const float4*>(&Bs[kk][tx*4]);
            float b[4] = {b4.x, b4.y, b4.z, b4.w};
            #pragma unroll
            for (int i = 0; i < 8; i++)
                #pragma unroll
                for (int j = 0; j < 4; j++)
                    acc[i][j] = fmaf(a[i], b[j], acc[i][j]);
        }
        __syncthreads();
    }
    #pragma unroll
    for (int i = 0; i < 8; i++) {
        int row = m0 + ty*8 + i;
        if (row >= M) continue;
        int col = tx * 4;
        float4* cp = reinterpret_cast<float4*>(&C[(long)row * 128 + col]);
        if (EPI == 0) {
            *cp = make_float4(acc[i][0], acc[i][1], acc[i][2], acc[i][3]);
        } else {
            float4 prev = *cp;
            *cp = make_float4(prev.x + acc[i][0] + bias[col],
                              prev.y + acc[i][1] + bias[col+1],
                              prev.z + acc[i][2] + bias[col+2],
                              prev.w + acc[i][3] + bias[col+3]);
        }
    }
}

__global__ void bn_stats_k(const float* __restrict__ h, float* __restrict__ colsum,
                           float* __restrict__ colsq) {
    int c = threadIdx.x;   // 128 threads
    float s = 0.f, s2 = 0.f;
    for (int r = blockIdx.x; r < NN; r += gridDim.x) {
        float x = h[(long)r * 128 + c];
        s += x; s2 += x * x;
    }
    atomicAdd(&colsum[c], s);
    atomicAdd(&colsq[c], s2);
}

__global__ void bn_apply_relu_k(float* __restrict__ h, const float* __restrict__ gamma,
                                const float* __restrict__ beta,
                                const float* __restrict__ colsum,
                                const float* __restrict__ colsq) {
    int idx = blockIdx.x * blockDim.x + threadIdx.x;
    if (idx >= ND) return;
    int c = idx & 127;
    const float invN = 1.f / (float)NN;
    float mean = colsum[c] * invN;
    float var  = colsq[c] * invN - mean * mean;
    float rstd = rsqrtf(var + 1e-5f);
    float x = (h[idx] - mean) * rstd * gamma[c] + beta[c];
    h[idx] = x > 0.f ? x : 0.f;
}

__global__ void attn_combine_k(const float* __restrict__ qa, const float* __restrict__ ska,
                               const float* __restrict__ vv, float* __restrict__ o) {
    int idx = blockIdx.x * blockDim.x + threadIdx.x;
    if (idx >= ND) return;
    float q = qa[idx];
    float l0 = q - ska[idx];
    float l1 = q - ska[ND + idx];
    float l2 = q - ska[2*ND + idx];
    float m = fmaxf(l0, fmaxf(l1, l2));
    float e0 = __expf(l0 - m), e1 = __expf(l1 - m), e2 = __expf(l2 - m);
    float inv = 1.f / (e0 + e1 + e2);
    o[idx] = (e0 * vv[idx] + e1 * vv[ND + idx] + e2 * vv[2*ND + idx]) * inv;
}

// -------- host --------

extern "C" void kernel_launch(void* const* d_in, const int* in_sizes, int n_in,
                              void* d_out, int out_size) {
    const float* n_emb = (const float*)d_in[0];
    const float* e_emb = (const float*)d_in[1];
    const float* m1_w1 = (const float*)d_in[2];
    const float* m1_gamma = (const float*)d_in[3];
    const float* m1_beta  = (const float*)d_in[4];
    const float* m1_w2 = (const float*)d_in[5];
    const float* m1_b2 = (const float*)d_in[6];
    const float* a1_wq = (const float*)d_in[7];
    const float* a1_wk = (const float*)d_in[8];
    const float* a1_wv = (const float*)d_in[9];
    const float* a1_wa = (const float*)d_in[10];
    // d_in[11] = a1_ba : softmax-shift invariant, unused
    const float* a1_wp = (const float*)d_in[12];
    const float* a1_bp = (const float*)d_in[13];
    const float* m2_w1 = (const float*)d_in[14];
    const float* m2_gamma = (const float*)d_in[15];
    const float* m2_beta  = (const float*)d_in[16];
    const float* m2_w2 = (const float*)d_in[17];
    const float* m2_b2 = (const float*)d_in[18];
    const float* a2_wq = (const float*)d_in[19];
    const float* a2_wk = (const float*)d_in[20];
    const float* a2_wv = (const float*)d_in[21];
    const float* a2_wa = (const float*)d_in[22];
    // d_in[23] = a2_ba : unused (softmax-shift invariant)
    const float* a2_wp = (const float*)d_in[24];
    const float* a2_bp = (const float*)d_in[25];
    const int* node_ind = (const int*)d_in[26];
    const int* edge_src = (const int*)d_in[27];
    const int* edge_dst = (const int*)d_in[28];

    float *feat, *t1, *t2, *key, *ska, *vv, *inv, *gscale, *colsum, *colsq, *wqa, *wka;
    int* cnt;
    cudaGetSymbolAddress((void**)&feat, g_feat);
    cudaGetSymbolAddress((void**)&t1, g_t1);
    cudaGetSymbolAddress((void**)&t2, g_t2);
    cudaGetSymbolAddress((void**)&key, g_key);
    cudaGetSymbolAddress((void**)&ska, g_ska);
    cudaGetSymbolAddress((void**)&vv, g_v);
    cudaGetSymbolAddress((void**)&cnt, g_cnt);
    cudaGetSymbolAddress((void**)&inv, g_inv);
    cudaGetSymbolAddress((void**)&gscale, g_gscale);
    cudaGetSymbolAddress((void**)&colsum, g_colsum);
    cudaGetSymbolAddress((void**)&colsq, g_colsq);
    cudaGetSymbolAddress((void**)&wqa, g_wqa);
    cudaGetSymbolAddress((void**)&wka, g_wka);

    const int TPB = 256;
    const int ND_BLK = (ND + TPB - 1) / TPB;          // 50000
    const int EDGE_BLK = (TT*EE*32 + TPB - 1) / TPB;  // 93750 (warp per edge)
    const int GEMM_BLK = (NN + 63) / 64;              // 1563

    // ---- setup ----
    cudaMemsetAsync(cnt, 0, TT*NN*sizeof(int), 0);
    count_k<<<(TT*EE + TPB - 1)/TPB, TPB>>>(edge_dst, cnt);
    prep_k<<<(NN + TPB - 1)/TPB, TPB>>>(cnt, inv, gscale);
    gather_feat_k<<<ND_BLK, TPB>>>(n_emb, node_ind, feat);

    const float* gcn_w1[2]    = {m1_w1, m2_w1};
    const float* gcn_gamma[2] = {m1_gamma, m2_gamma};
    const float* gcn_beta[2]  = {m1_beta, m2_beta};
    const float* gcn_w2[2]    = {m1_w2, m2_w2};
    const float* gcn_b2[2]    = {m1_b2, m2_b2};
    const float* at_wq[2] = {a1_wq, a2_wq};
    const float* at_wk[2] = {a1_wk, a2_wk};
    const float* at_wv[2] = {a1_wv, a2_wv};
    const float* at_wa[2] = {a1_wa, a2_wa};
    const float* at_wp[2] = {a1_wp, a2_wp};
    const float* at_bp[2] = {a1_bp, a2_bp};

    for (int L = 0; L < 2; L++) {
        // ---- GCN layer ----
        init_acc_k<<<ND_BLK, TPB>>>(feat, gscale, t1);
        gcn_edge_k<<<EDGE_BLK, TPB>>>(feat, e_emb, edge_src, edge_dst, inv, t1);
        gemm128<0><<<GEMM_BLK, 256>>>(t1, gcn_w1[L], t2, nullptr, NN);
        cudaMemsetAsync(colsum, 0, DD*sizeof(float), 0);
        cudaMemsetAsync(colsq, 0, DD*sizeof(float), 0);
        bn_stats_k<<<512, 128>>>(t2, colsum, colsq);
        bn_apply_relu_k<<<ND_BLK, TPB>>>(t2, gcn_gamma[L], gcn_beta[L], colsum, colsq);
        gemm128<1><<<GEMM_BLK, 256>>>(t2, gcn_w2[L], feat, gcn_b2[L], NN);

        // ---- Attention layer ----
        gemm128<0><<<2, 256>>>(at_wq[L], at_wa[L], wqa, nullptr, 128);
        gemm128<0><<<2, 256>>>(at_wk[L], at_wa[L], wka, nullptr, 128);
        cudaMemsetAsync(key, 0, (size_t)3*ND*sizeof(float), 0);
        attn_edge_k<<<EDGE_BLK, TPB>>>(feat, e_emb, edge_src, edge_dst, inv, key);
        gemm128<0><<<GEMM_BLK, 256>>>(feat, wqa, t1, nullptr, NN);   // qa
        for (int t = 0; t < 3; t++)
            gemm128<0><<<GEMM_BLK, 256>>>(key + (long)t*ND, wka, ska + (long)t*ND, nullptr, NN);
        for (int t = 0; t < 3; t++)
            gemm128<0><<<GEMM_BLK, 256>>>(key + (long)t*ND, at_wv[L], vv + (long)t*ND, nullptr, NN);
        attn_combine_k<<<ND_BLK, TPB>>>(t1, ska, vv, t2);
        gemm128<1><<<GEMM_BLK, 256>>>(t2, at_wp[L], feat, at_bp[L], NN);
    }

    // ---- output: (feat, e_emb) ----
    cudaMemcpyAsync(d_out, feat, (size_t)ND*sizeof(float), cudaMemcpyDeviceToDevice, 0);
    if (out_size >= ND + TT*DD) {
        cudaMemcpyAsync((float*)d_out + ND, e_emb, TT*DD*sizeof(float),
                        cudaMemcpyDeviceToDevice, 0);
    }
}

// round 4
// speedup vs baseline: 2.1351x; 2.1351x over previous
#include <cuda_runtime.h>
#include <cuda_bf16.h>
#include <cstdint>
#include <math.h>

#define NN 100000
#define DD 128
#define EE 250000
#define TT 3
#define ND (NN*DD)

// -------- scratch (device globals; no runtime allocation) --------
__device__ float g_feat[ND];
__device__ float g_t1[ND];
__device__ float g_t2[ND];
__device__ float g_key[3*ND];
__device__ float g_ska[3*ND];
__device__ float g_v[3*ND];
__device__ int   g_cnt[TT*NN];
__device__ float g_inv[TT*NN];
__device__ float g_gscale[NN];
__device__ float g_colsum[DD];
__device__ float g_colsq[DD];
__device__ float g_wqa[DD*DD];
__device__ float g_wka[DD*DD];

// -------- small kernels --------

__global__ void gather_feat_k(const float* __restrict__ n_emb, const int* __restrict__ ind,
                              float* __restrict__ feat) {
    int idx = blockIdx.x * blockDim.x + threadIdx.x;
    if (idx >= ND) return;
    int n = idx >> 7;
    feat[idx] = n_emb[(long)ind[n] * DD + (idx & 127)];
}

__global__ void count_k(const int* __restrict__ dst, int* __restrict__ cnt) {
    int e = blockIdx.x * blockDim.x + threadIdx.x;
    if (e >= TT*EE) return;
    int t = e / EE;
    atomicAdd(&cnt[t * NN + dst[e]], 1);
}

__global__ void prep_k(const int* __restrict__ cnt, float* __restrict__ inv,
                       float* __restrict__ gscale) {
    int n = blockIdx.x * blockDim.x + threadIdx.x;
    if (n >= NN) return;
    int c0 = cnt[n], c1 = cnt[NN + n], c2 = cnt[2*NN + n];
    inv[n]        = 1.f / (float)max(c0, 1);
    inv[NN + n]   = 1.f / (float)max(c1, 1);
    inv[2*NN + n] = 1.f / (float)max(c2, 1);
    gscale[n] = (float)((c0 > 0) + (c1 > 0) + (c2 > 0));
}

__global__ void init_acc_k(const float* __restrict__ feat, const float* __restrict__ gscale,
                           float* __restrict__ acc) {
    int idx = blockIdx.x * blockDim.x + threadIdx.x;
    if (idx >= ND) return;
    acc[idx] = feat[idx] * gscale[idx >> 7];
}

__device__ __forceinline__ void red_add_v4(float* p, float4 v) {
    asm volatile("red.global.add.v4.f32 [%0], {%1,%2,%3,%4};"
                 :: "l"(p), "f"(v.x), "f"(v.y), "f"(v.z), "f"(v.w) : "memory");
}

__global__ void gcn_edge_k(const float* __restrict__ feat, const float* __restrict__ emb,
                           const int* __restrict__ src, const int* __restrict__ dst,
                           const float* __restrict__ inv, float* __restrict__ acc) {
    int gw = (blockIdx.x * blockDim.x + threadIdx.x) >> 5;
    int lane = threadIdx.x & 31;
    if (gw >= TT*EE) return;
    int t = gw / EE;
    int s = src[gw], d = dst[gw];
    float w = inv[t * NN + d];
    float4 f = reinterpret_cast<const float4*>(feat + (long)s * DD)[lane];
    float4 e = reinterpret_cast<const float4*>(emb + t * DD)[lane];
    float4 v = make_float4(-f.x*e.x*w, -f.y*e.y*w, -f.z*e.z*w, -f.w*e.w*w);
    red_add_v4(acc + (long)d * DD + lane*4, v);
}

__global__ void attn_edge_k(const float* __restrict__ feat, const float* __restrict__ emb,
                            const int* __restrict__ src, const int* __restrict__ dst,
                            const float* __restrict__ inv, float* __restrict__ key) {
    int gw = (blockIdx.x * blockDim.x + threadIdx.x) >> 5;
    int lane = threadIdx.x & 31;
    if (gw >= TT*EE) return;
    int t = gw / EE;
    int s = src[gw], d = dst[gw];
    float w = inv[t * NN + d];
    float4 f = reinterpret_cast<const float4*>(feat + (long)s * DD)[lane];
    float4 e = reinterpret_cast<const float4*>(emb + t * DD)[lane];
    float4 v = make_float4(f.x*e.x*w, f.y*e.y*w, f.z*e.z*w, f.w*e.w*w);
    red_add_v4(key + (long)t * ND + (long)d * DD + lane*4, v);
}

// -------- tf32 tensor-core GEMM: C[M,128] = A[M,128] @ B[128,128] --------
// EPI==1: C += acc + bias[col]  (C pre-contains residual)

__device__ __forceinline__ uint32_t f2tf32(float f) {
    uint32_t o;
    asm("cvt.rna.tf32.f32 %0, %1;" : "=r"(o) : "f"(f));
    return o;
}

__device__ __forceinline__ void mma_tf32(float* c, const uint32_t* a, const uint32_t* b) {
    asm volatile("mma.sync.aligned.m16n8k8.row.col.f32.tf32.tf32.f32 "
                 "{%0,%1,%2,%3}, {%4,%5,%6,%7}, {%8,%9}, {%0,%1,%2,%3};"
                 : "+f"(c[0]), "+f"(c[1]), "+f"(c[2]), "+f"(c[3])
                 : "r"(a[0]), "r"(a[1]), "r"(a[2]), "r"(a[3]), "r"(b[0]), "r"(b[1]));
}

template<int EPI>
__global__ __launch_bounds__(256) void gemm_tc(const float* __restrict__ A,
                                               const float* __restrict__ B,
                                               float* __restrict__ C,
                                               const float* __restrict__ bias, int M) {
    __shared__ uint32_t As[128][36];   // +4 pad: conflict-free frag loads
    __shared__ uint32_t Bs[32][136];   // +8 pad
    int tid = threadIdx.x;
    int lane = tid & 31, wid = tid >> 5;
    int wm = wid & 3, wn = wid >> 2;          // 4x2 warp grid: 32-row x 64-col warp tiles
    int g = lane >> 2, q = lane & 3;
    long m0 = (long)blockIdx.x * 128;

    float acc[2][8][4];
    #pragma unroll
    for (int mt = 0; mt < 2; mt++)
        #pragma unroll
        for (int nt = 0; nt < 8; nt++)
            #pragma unroll
            for (int i = 0; i < 4; i++) acc[mt][nt][i] = 0.f;

    for (int k0 = 0; k0 < 128; k0 += 32) {
        // stage A chunk [128 x 32]
        #pragma unroll
        for (int i = 0; i < 4; i++) {
            int idx = (tid + 256 * i) * 4;
            int r = idx >> 5, c = idx & 31;
            float4 v = make_float4(0.f, 0.f, 0.f, 0.f);
            if (m0 + r < M) v = *reinterpret_cast<const float4*>(A + (m0 + r) * 128 + k0 + c);
            uint4 t = make_uint4(f2tf32(v.x), f2tf32(v.y), f2tf32(v.z), f2tf32(v.w));
            *reinterpret_cast<uint4*>(&As[r][c]) = t;
        }
        // stage B chunk [32 x 128]
        #pragma unroll
        for (int i = 0; i < 4; i++) {
            int idx = (tid + 256 * i) * 4;
            int r = idx >> 7, c = idx & 127;
            float4 v = *reinterpret_cast<const float4*>(B + (k0 + r) * 128 + c);
            uint4 t = make_uint4(f2tf32(v.x), f2tf32(v.y), f2tf32(v.z), f2tf32(v.w));
            *reinterpret_cast<uint4*>(&Bs[r][c]) = t;
        }
        __syncthreads();

        #pragma unroll
        for (int ks = 0; ks < 4; ks++) {
            int kc = ks * 8;
            uint32_t a[2][4], b[8][2];
            #pragma unroll
            for (int mt = 0; mt < 2; mt++) {
                int row = wm * 32 + mt * 16 + g;
                a[mt][0] = As[row][kc + q];
                a[mt][1] = As[row + 8][kc + q];
                a[mt][2] = As[row][kc + q + 4];
                a[mt][3] = As[row + 8][kc + q + 4];
            }
            #pragma unroll
            for (int nt = 0; nt < 8; nt++) {
                int col = wn * 64 + nt * 8 + g;
                b[nt][0] = Bs[kc + q][col];
                b[nt][1] = Bs[kc + q + 4][col];
            }
            #pragma unroll
            for (int mt = 0; mt < 2; mt++)
                #pragma unroll
                for (int nt = 0; nt < 8; nt++)
                    mma_tf32(acc[mt][nt], a[mt], b[nt]);
        }
        __syncthreads();
    }

    // epilogue
    #pragma unroll
    for (int mt = 0; mt < 2; mt++) {
        #pragma unroll
        for (int h = 0; h < 2; h++) {
            long row = m0 + wm * 32 + mt * 16 + g + h * 8;
            if (row >= M) continue;
            #pragma unroll
            for (int nt = 0; nt < 8; nt++) {
                int col = wn * 64 + nt * 8 + q * 2;
                float2* cp = reinterpret_cast<float2*>(&C[row * 128 + col]);
                float v0 = acc[mt][nt][h * 2], v1 = acc[mt][nt][h * 2 + 1];
                if (EPI == 0) {
                    *cp = make_float2(v0, v1);
                } else {
                    float2 prev = *cp;
                    *cp = make_float2(prev.x + v0 + bias[col], prev.y + v1 + bias[col + 1]);
                }
            }
        }
    }
}

// -------- BN / softmax fusion kernels --------

__global__ void bn_stats_k(const float* __restrict__ h, float* __restrict__ colsum,
                           float* __restrict__ colsq) {
    int c = threadIdx.x;
    float s = 0.f, s2 = 0.f;
    for (int r = blockIdx.x; r < NN; r += gridDim.x) {
        float x = h[(long)r * 128 + c];
        s += x; s2 += x * x;
    }
    atomicAdd(&colsum[c], s);
    atomicAdd(&colsq[c], s2);
}

__global__ void bn_apply_relu_k(float* __restrict__ h, const float* __restrict__ gamma,
                                const float* __restrict__ beta,
                                const float* __restrict__ colsum,
                                const float* __restrict__ colsq) {
    int idx = blockIdx.x * blockDim.x + threadIdx.x;
    if (idx >= ND) return;
    int c = idx & 127;
    const float invN = 1.f / (float)NN;
    float mean = colsum[c] * invN;
    float var  = colsq[c] * invN - mean * mean;
    float rstd = rsqrtf(var + 1e-5f);
    float x = (h[idx] - mean) * rstd * gamma[c] + beta[c];
    h[idx] = x > 0.f ? x : 0.f;
}

__global__ void attn_combine_k(const float* __restrict__ qa, const float* __restrict__ ska,
                               const float* __restrict__ vv, float* __restrict__ o) {
    int idx = blockIdx.x * blockDim.x + threadIdx.x;
    if (idx >= ND) return;
    float q = qa[idx];
    float l0 = q - ska[idx];
    float l1 = q - ska[ND + idx];
    float l2 = q - ska[2*ND + idx];
    float m = fmaxf(l0, fmaxf(l1, l2));
    float e0 = __expf(l0 - m), e1 = __expf(l1 - m), e2 = __expf(l2 - m);
    float inv = 1.f / (e0 + e1 + e2);
    o[idx] = (e0 * vv[idx] + e1 * vv[ND + idx] + e2 * vv[2*ND + idx]) * inv;
}

// -------- host --------

extern "C" void kernel_launch(void* const* d_in, const int* in_sizes, int n_in,
                              void* d_out, int out_size) {
    const float* e_emb = (const float*)d_in[1];
    const int* node_ind = (const int*)d_in[26];
    const int* edge_src = (const int*)d_in[27];
    const int* edge_dst = (const int*)d_in[28];

    float *feat, *t1, *t2, *key, *ska, *vv, *inv, *gscale, *colsum, *colsq, *wqa, *wka;
    int* cnt;
    cudaGetSymbolAddress((void**)&feat, g_feat);
    cudaGetSymbolAddress((void**)&t1, g_t1);
    cudaGetSymbolAddress((void**)&t2, g_t2);
    cudaGetSymbolAddress((void**)&key, g_key);
    cudaGetSymbolAddress((void**)&ska, g_ska);
    cudaGetSymbolAddress((void**)&vv, g_v);
    cudaGetSymbolAddress((void**)&cnt, g_cnt);
    cudaGetSymbolAddress((void**)&inv, g_inv);
    cudaGetSymbolAddress((void**)&gscale, g_gscale);
    cudaGetSymbolAddress((void**)&colsum, g_colsum);
    cudaGetSymbolAddress((void**)&colsq, g_colsq);
    cudaGetSymbolAddress((void**)&wqa, g_wqa);
    cudaGetSymbolAddress((void**)&wka, g_wka);

    const int TPB = 256;
    const int ND_BLK = (ND + TPB - 1) / TPB;
    const int EDGE_BLK = (TT*EE*32 + TPB - 1) / TPB;
    const int G1 = (NN + 127) / 128;       // 782
    const int G3 = (TT*NN + 127) / 128;    // 2344

    cudaMemsetAsync(cnt, 0, TT*NN*sizeof(int), 0);
    count_k<<<(TT*EE + TPB - 1)/TPB, TPB>>>(edge_dst, cnt);
    prep_k<<<(NN + TPB - 1)/TPB, TPB>>>(cnt, inv, gscale);
    gather_feat_k<<<ND_BLK, TPB>>>((const float*)d_in[0], node_ind, feat);

    const float* gcn_w1[2]    = {(const float*)d_in[2],  (const float*)d_in[14]};
    const float* gcn_gamma[2] = {(const float*)d_in[3],  (const float*)d_in[15]};
    const float* gcn_beta[2]  = {(const float*)d_in[4],  (const float*)d_in[16]};
    const float* gcn_w2[2]    = {(const float*)d_in[5],  (const float*)d_in[17]};
    const float* gcn_b2[2]    = {(const float*)d_in[6],  (const float*)d_in[18]};
    const float* at_wq[2]     = {(const float*)d_in[7],  (const float*)d_in[19]};
    const float* at_wk[2]     = {(const float*)d_in[8],  (const float*)d_in[20]};
    const float* at_wv[2]     = {(const float*)d_in[9],  (const float*)d_in[21]};
    const float* at_wa[2]     = {(const float*)d_in[10], (const float*)d_in[22]};
    const float* at_wp[2]     = {(const float*)d_in[12], (const float*)d_in[24]};
    const float* at_bp[2]     = {(const float*)d_in[13], (const float*)d_in[25]};
    // ba (d_in[11], d_in[23]) drop out: softmax is shift-invariant per (n,f).

    for (int L = 0; L < 2; L++) {
        // ---- GCN layer ----
        init_acc_k<<<ND_BLK, TPB>>>(feat, gscale, t1);
        gcn_edge_k<<<EDGE_BLK, TPB>>>(feat, e_emb, edge_src, edge_dst, inv, t1);
        gemm_tc<0><<<G1, 256>>>(t1, gcn_w1[L], t2, nullptr, NN);
        cudaMemsetAsync(colsum, 0, DD*sizeof(float), 0);
        cudaMemsetAsync(colsq, 0, DD*sizeof(float), 0);
        bn_stats_k<<<512, 128>>>(t2, colsum, colsq);
        bn_apply_relu_k<<<ND_BLK, TPB>>>(t2, gcn_gamma[L], gcn_beta[L], colsum, colsq);
        gemm_tc<1><<<G1, 256>>>(t2, gcn_w2[L], feat, gcn_b2[L], NN);

        // ---- Attention layer ----
        gemm_tc<0><<<1, 256>>>(at_wq[L], at_wa[L], wqa, nullptr, 128);
        gemm_tc<0><<<1, 256>>>(at_wk[L], at_wa[L], wka, nullptr, 128);
        cudaMemsetAsync(key, 0, (size_t)3*ND*sizeof(float), 0);
        attn_edge_k<<<EDGE_BLK, TPB>>>(feat, e_emb, edge_src, edge_dst, inv, key);
        gemm_tc<0><<<G1, 256>>>(feat, wqa, t1, nullptr, NN);                 // qa
        gemm_tc<0><<<G3, 256>>>(key, wka, ska, nullptr, TT*NN);              // ska (3 etypes batched)
        gemm_tc<0><<<G3, 256>>>(key, at_wv[L], vv, nullptr, TT*NN);          // v   (3 etypes batched)
        attn_combine_k<<<ND_BLK, TPB>>>(t1, ska, vv, t2);
        gemm_tc<1><<<G1, 256>>>(t2, at_wp[L], feat, at_bp[L], NN);
    }

    cudaMemcpyAsync(d_out, feat, (size_t)ND*sizeof(float), cudaMemcpyDeviceToDevice, 0);
    if (out_size >= ND + TT*DD) {
        cudaMemcpyAsync((float*)d_out + ND, e_emb, TT*DD*sizeof(float),
                        cudaMemcpyDeviceToDevice, 0);
    }
}